// round 15
// baseline (speedup 1.0000x reference)
#include <cuda_runtime.h>
#include <cuda_bf16.h>
#include <cuda_fp16.h>
#include <cstdint>

// ---------------------------------------------------------------------------
// GraphSAGE: out = normalize( [x | segsum(vals * x[cols])] @ W^T + b )
// N=100000, E=1600000, IN_F=OUT_F=128, rows sorted.
//
//   K1: prep — row_start init + W fp16 image (tiny).
//   K1b: rowidx — CSR row_start gap-fill from sorted rows.
//   K2: SpMM — warp-per-row with cp.async smem ring gather: blocks of 8
//       edges double-buffered; LDGSTS decouples L2 latency from the FMA
//       chain (rounds 9-14 showed reg-scoreboard latency was the binder).
//       Emits neighbor fp16 + x fp16.
//   K3: fp16 HMMA GEMM, W resident in smem, A via cp.async double buffer,
//       2 CTAs/SM, fused bias + row L2-normalize.
// ---------------------------------------------------------------------------

#define NNODES   100000
#define INF      128
#define TWOK     256
#define OUTF     128

__device__ __half g_xh[(size_t)NNODES * INF];
__device__ __half g_nh[(size_t)NNODES * INF];
__device__ int    g_rowstart[NNODES + 1];
__device__ __align__(128) unsigned char g_Wh_img[65536];

// ---------------------------------------------------------------------------
// helpers
// ---------------------------------------------------------------------------
__device__ __forceinline__ uint32_t smem_u32(const void* p) {
    uint32_t a;
    asm("{ .reg .u64 t; cvta.to.shared.u64 t, %1; cvt.u32.u64 %0, t; }"
        : "=r"(a) : "l"(p));
    return a;
}
__device__ __forceinline__ uint32_t sw128(uint32_t off) {
    return off ^ ((off >> 3) & 0x70);
}
__device__ __forceinline__ void ldsm_x4(uint32_t& r0, uint32_t& r1,
                                        uint32_t& r2, uint32_t& r3, uint32_t a) {
    asm volatile("ldmatrix.sync.aligned.m8n8.x4.shared.b16 {%0,%1,%2,%3}, [%4];"
                 : "=r"(r0), "=r"(r1), "=r"(r2), "=r"(r3) : "r"(a));
}
__device__ __forceinline__ void mma_f16(float* c, const uint32_t* a,
                                        const uint32_t* b) {
    asm volatile(
        "mma.sync.aligned.m16n8k16.row.col.f32.f16.f16.f32 "
        "{%0,%1,%2,%3}, {%4,%5,%6,%7}, {%8,%9}, {%0,%1,%2,%3};"
        : "+f"(c[0]), "+f"(c[1]), "+f"(c[2]), "+f"(c[3])
        : "r"(a[0]), "r"(a[1]), "r"(a[2]), "r"(a[3]), "r"(b[0]), "r"(b[1]));
}
#define CP_ASYNC16(dst, src) \
    asm volatile("cp.async.cg.shared.global [%0], [%1], 16;" :: "r"(dst), "l"(src))
#define CP_ASYNC16Z(dst, src, sz) \
    asm volatile("cp.async.cg.shared.global [%0], [%1], 16, %2;" \
                 :: "r"(dst), "l"(src), "r"(sz))
#define CP_COMMIT() asm volatile("cp.async.commit_group;" ::: "memory")
#define CP_WAIT1()  asm volatile("cp.async.wait_group 1;" ::: "memory")
#define CP_WAIT0()  asm volatile("cp.async.wait_group 0;" ::: "memory")

// ---------------------------------------------------------------------------
// K1: row_start init + W fp16 image (tiny).
// ---------------------------------------------------------------------------
__global__ void prep_kernel(const float* __restrict__ W, int E, int N) {
    int i = blockIdx.x * blockDim.x + threadIdx.x;
    if (i <= N) g_rowstart[i] = E;
    if (i < 8192) {                     // W image: 8192 float4s
        int row   = i >> 6;
        int kf    = i & 63;
        int chunk = kf >> 4;
        int k4    = kf & 15;
        float4 wv = *reinterpret_cast<const float4*>(W + row * TWOK + chunk * 64 + k4 * 4);
        __half2 h0 = __floats2half2_rn(wv.x, wv.y);
        __half2 h1 = __floats2half2_rn(wv.z, wv.w);
        uint32_t off = chunk * 16384 + sw128((uint32_t)(row * 128 + k4 * 8));
        *reinterpret_cast<uint2*>(g_Wh_img + off) =
            make_uint2(*reinterpret_cast<uint32_t*>(&h0),
                       *reinterpret_cast<uint32_t*>(&h1));
    }
}

// ---------------------------------------------------------------------------
// K1b: CSR gap-fill from sorted rows.
// ---------------------------------------------------------------------------
__global__ void rowidx_kernel(const int* __restrict__ rows, int E) {
    int e = blockIdx.x * blockDim.x + threadIdx.x;
    if (e >= E) return;
    int r = __ldg(rows + e);
    int prev = (e == 0) ? -1 : __ldg(rows + e - 1);
    if (r != prev) {
        for (int q = prev + 1; q <= r; q++) g_rowstart[q] = e;
    }
}

// ---------------------------------------------------------------------------
// K2: SpMM, warp per row, cp.async smem-ring gather.
//   Per warp: 2 buffers x 8 edges x 512B = 8KB smem. Blocks of 8 edges are
//   cp.async'd (16B per lane) and consumed one block behind (wait_group 1).
//   Lane owns dims [4l,4l+4). Each lane reads back only its own 16B.
// ---------------------------------------------------------------------------
#define QD      8
#define WBUF    (2 * QD * 512)          // 8KB per warp
#define SPMM_SMEM (8 * WBUF)            // 64KB per 256-thread CTA

__global__ void __launch_bounds__(256)
spmm_kernel(const float* __restrict__ x,
            const int*   __restrict__ cols,
            const float* __restrict__ vals,
            int N) {
    extern __shared__ char sm[];
    int wib  = threadIdx.x >> 5;
    int lane = threadIdx.x & 31;
    int warp = (blockIdx.x * blockDim.x + threadIdx.x) >> 5;
    if (warp >= N) return;
    int row = warp;

    uint32_t wbase = smem_u32(sm) + wib * WBUF;
    const char* wdata = sm + wib * WBUF;
    const char* xb = reinterpret_cast<const char*>(x);

    int s  = __ldg(g_rowstart + row);
    int en = __ldg(g_rowstart + row + 1);

    float4 acc = make_float4(0.f, 0.f, 0.f, 0.f);

    for (int e0 = s; e0 < en; e0 += 32) {
        int   idx = e0 + lane;
        bool  vd  = idx < en;
        int   c0  = vd ? __ldg(cols + idx) : 0;
        float v0  = vd ? __ldg(vals + idx) : 0.f;
        int n  = min(32, en - e0);
        int nb = (n + QD - 1) / QD;

        // issue block 0
        {
            int m0 = min(QD, n);
            for (int j = 0; j < m0; j++) {
                int cj = __shfl_sync(0xffffffffu, c0, j);
                CP_ASYNC16(wbase + j * 512 + lane * 16,
                           xb + (size_t)cj * 512 + lane * 16);
            }
            CP_COMMIT();
        }

        for (int bi = 0; bi < nb; bi++) {
            if (bi + 1 < nb) {
                int b1 = (bi + 1) * QD;
                int m1 = min(QD, n - b1);
                uint32_t dst = wbase + ((bi + 1) & 1) * (QD * 512);
                for (int j = 0; j < m1; j++) {
                    int cj = __shfl_sync(0xffffffffu, c0, b1 + j);
                    CP_ASYNC16(dst + j * 512 + lane * 16,
                               xb + (size_t)cj * 512 + lane * 16);
                }
                CP_COMMIT();
                CP_WAIT1();
            } else {
                CP_WAIT0();
            }

            int b = bi * QD;
            int m = min(QD, n - b);
            const char* sbuf = wdata + (bi & 1) * (QD * 512);
            for (int j = 0; j < m; j++) {
                float vj = __shfl_sync(0xffffffffu, v0, b + j);
                float4 xv = *reinterpret_cast<const float4*>(
                    sbuf + j * 512 + lane * 16);
                acc.x = fmaf(vj, xv.x, acc.x);
                acc.y = fmaf(vj, xv.y, acc.y);
                acc.z = fmaf(vj, xv.z, acc.z);
                acc.w = fmaf(vj, xv.w, acc.w);
            }
        }
    }

    __half2 h0 = __floats2half2_rn(acc.x, acc.y);
    __half2 h1 = __floats2half2_rn(acc.z, acc.w);
    reinterpret_cast<uint2*>(g_nh)[(size_t)row * 32 + lane] =
        make_uint2(*reinterpret_cast<uint32_t*>(&h0),
                   *reinterpret_cast<uint32_t*>(&h1));

    // x row -> fp16 (feeds GEMM chunks 0-1)
    float4 xr = reinterpret_cast<const float4*>(x)[(size_t)row * 32 + lane];
    __half2 g0 = __floats2half2_rn(xr.x, xr.y);
    __half2 g1 = __floats2half2_rn(xr.z, xr.w);
    reinterpret_cast<uint2*>(g_xh)[(size_t)row * 32 + lane] =
        make_uint2(*reinterpret_cast<uint32_t*>(&g0),
                   *reinterpret_cast<uint32_t*>(&g1));
}

// ---------------------------------------------------------------------------
// K3: fp16 HMMA GEMM + bias + L2 normalize. (unchanged)
// ---------------------------------------------------------------------------
#define SM_W    0
#define SM_A    65536                 // 2 stages x 16384
#define SM_BIAS (SM_A + 32768)
#define SM_RSS  (SM_BIAS + 512)
#define SM_TOTAL (SM_RSS + 2048)

__global__ void __launch_bounds__(256, 2)
gemm_norm_kernel(const float* __restrict__ b,
                 float* __restrict__ out,
                 int N) {
    extern __shared__ char smem[];
    uint32_t sb = smem_u32(smem);
    float* bias = reinterpret_cast<float*>(smem + SM_BIAS);
    float (*rss)[128] = reinterpret_cast<float (*)[128]>(smem + SM_RSS);

    int t    = threadIdx.x;
    int wid  = t >> 5;
    int lane = t & 31;
    int warp_m = wid & 1;
    int warp_n = wid >> 1;
    int rowBase = blockIdx.x * 128;

    #pragma unroll
    for (int j = 0; j < 16; j++)
        CP_ASYNC16(sb + SM_W + t * 16 + j * 4096, g_Wh_img + t * 16 + j * 4096);

    const char* xb = reinterpret_cast<const char*>(g_xh);
    const char* nb = reinterpret_cast<const char*>(g_nh);

    auto stageA = [&](int c) {
        const char* srcb = (c < 2) ? (xb + c * 128) : (nb + (c - 2) * 128);
        uint32_t dstb = sb + SM_A + (c & 1) * 16384;
        #pragma unroll
        for (int j = 0; j < 4; j++) {
            int i  = t + 256 * j;
            int r  = i >> 3;
            int u8 = i & 7;
            int gr = rowBase + r;
            uint32_t sz = (gr < N) ? 16u : 0u;
            CP_ASYNC16Z(dstb + sw128((uint32_t)(r * 128 + u8 * 16)),
                        srcb + (size_t)gr * 256 + u8 * 16, sz);
        }
    };

    stageA(0); CP_COMMIT();
    stageA(1); CP_COMMIT();

    if (t < OUTF) bias[t] = __ldg(b + t);

    float acc[4][4][4];
    #pragma unroll
    for (int mi = 0; mi < 4; mi++)
        #pragma unroll
        for (int ni = 0; ni < 4; ni++)
            #pragma unroll
            for (int r = 0; r < 4; r++) acc[mi][ni][r] = 0.f;

    int aRow  = warp_m * 64 + (lane & 15);
    int aK8   = (lane >> 4) * 8;
    int bRowX = warp_n * 32 + (lane & 7) + ((lane >> 4) & 1) * 8;
    int bK8   = ((lane >> 3) & 1) * 8;

    #pragma unroll
    for (int c = 0; c < 4; c++) {
        if (c < 3) { CP_WAIT1(); } else { CP_WAIT0(); }
        __syncthreads();

        uint32_t aBuf  = sb + SM_A + (c & 1) * 16384;
        uint32_t wBase = sb + SM_W + c * 16384;
        #pragma unroll
        for (int kk = 0; kk < 64; kk += 16) {
            uint32_t a[4][4], bb[4][2];
            #pragma unroll
            for (int mi = 0; mi < 4; mi++) {
                uint32_t off = sw128((uint32_t)((aRow + mi * 16) * 128
                                                + (kk + aK8) * 2));
                ldsm_x4(a[mi][0], a[mi][1], a[mi][2], a[mi][3], aBuf + off);
            }
            #pragma unroll
            for (int p = 0; p < 2; p++) {
                uint32_t off = sw128((uint32_t)((bRowX + p * 16) * 128
                                                + (kk + bK8) * 2));
                ldsm_x4(bb[2*p][0], bb[2*p][1], bb[2*p+1][0], bb[2*p+1][1],
                        wBase + off);
            }
            #pragma unroll
            for (int mi = 0; mi < 4; mi++)
                #pragma unroll
                for (int ni = 0; ni < 4; ni++)
                    mma_f16(acc[mi][ni], a[mi], bb[ni]);
        }

        if (c < 2) {
            __syncthreads();
            stageA(c + 2); CP_COMMIT();
        }
    }

    // ---- epilogue ----
    int colBase = warp_n * 32 + 2 * (lane & 3);
    #pragma unroll
    for (int mi = 0; mi < 4; mi++)
        #pragma unroll
        for (int ni = 0; ni < 4; ni++) {
            float b0 = bias[colBase + ni * 8];
            float b1 = bias[colBase + ni * 8 + 1];
            acc[mi][ni][0] += b0;  acc[mi][ni][1] += b1;
            acc[mi][ni][2] += b0;  acc[mi][ni][3] += b1;
        }

    #pragma unroll
    for (int mi = 0; mi < 4; mi++) {
        #pragma unroll
        for (int half = 0; half < 2; half++) {
            float s = 0.f;
            #pragma unroll
            for (int ni = 0; ni < 4; ni++) {
                float c0 = acc[mi][ni][half * 2 + 0];
                float c1 = acc[mi][ni][half * 2 + 1];
                s = fmaf(c0, c0, s);
                s = fmaf(c1, c1, s);
            }
            s += __shfl_xor_sync(0xffffffffu, s, 1);
            s += __shfl_xor_sync(0xffffffffu, s, 2);
            if ((lane & 3) == 0)
                rss[warp_n][warp_m * 64 + mi * 16 + half * 8 + (lane >> 2)] = s;
        }
    }
    __syncthreads();

    float2* out2 = reinterpret_cast<float2*>(out);
    #pragma unroll
    for (int mi = 0; mi < 4; mi++) {
        #pragma unroll
        for (int half = 0; half < 2; half++) {
            int rl  = warp_m * 64 + mi * 16 + half * 8 + (lane >> 2);
            int row = rowBase + rl;
            if (row < N) {
                float ss = rss[0][rl] + rss[1][rl] + rss[2][rl] + rss[3][rl];
                float scale = 1.f / fmaxf(sqrtf(ss), 1e-12f);
                #pragma unroll
                for (int ni = 0; ni < 4; ni++) {
                    float2 o;
                    o.x = acc[mi][ni][half * 2 + 0] * scale;
                    o.y = acc[mi][ni][half * 2 + 1] * scale;
                    out2[(size_t)row * 64 + (colBase + ni * 8) / 2] = o;
                }
            }
        }
    }
}

// ---------------------------------------------------------------------------
// Launch
// ---------------------------------------------------------------------------
extern "C" void kernel_launch(void* const* d_in, const int* in_sizes, int n_in,
                              void* d_out, int out_size) {
    const float* x    = (const float*)d_in[0];
    const int*   rows = (const int*)  d_in[1];
    const int*   cols = (const int*)  d_in[2];
    const float* vals = (const float*)d_in[3];
    const float* W    = (const float*)d_in[4];
    const float* b    = (const float*)d_in[5];
    float*       out  = (float*)d_out;

    int N = in_sizes[0] / INF;
    int E = in_sizes[1];

    cudaFuncSetAttribute(gemm_norm_kernel,
                         cudaFuncAttributeMaxDynamicSharedMemorySize, SM_TOTAL);
    cudaFuncSetAttribute(spmm_kernel,
                         cudaFuncAttributeMaxDynamicSharedMemorySize, SPMM_SMEM);

    // K1: row_start init + W image (tiny)
    prep_kernel<<<(N + 256) / 256, 256>>>(W, E, N);

    // K1b: CSR row_start gap-fill
    rowidx_kernel<<<(E + 255) / 256, 256>>>(rows, E);

    // K2: SpMM (warp per row, cp.async ring gather; emits x fp16)
    int blocks = (N * 32 + 255) / 256;
    spmm_kernel<<<blocks, 256, SPMM_SMEM>>>(x, cols, vals, N);

    // K3: fp16 HMMA GEMM + bias + normalize
    gemm_norm_kernel<<<(N + 127) / 128, 256, SM_TOTAL>>>(b, out, N);
}

// round 16
// speedup vs baseline: 1.3938x; 1.3938x over previous
#include <cuda_runtime.h>
#include <cuda_bf16.h>
#include <cuda_fp16.h>
#include <cstdint>

// ---------------------------------------------------------------------------
// GraphSAGE: out = normalize( [x | segsum(vals * x[cols])] @ W^T + b )
// N=100000, E=1600000, IN_F=OUT_F=128, rows sorted.
//
//   K1: prep — W fp16 SW128 image only (tiny).
//   K1b: rowidx — CSR gap-fill from sorted rows; last thread fills tail + [N].
//   K2: SpMM — round-9 proven body exactly (warp-per-row, coalesced metadata,
//       2-way shfl, MLP2, fp32 gather), writes neighbor fp16. No x-conv tail.
//   K3: fp16 HMMA GEMM: chunks 0-1 staged inline from fp32 x (reg cvt ->
//       swizzled STS; removes the x->fp16 prepass entirely), chunks 2-3 via
//       cp.async from nh. 2 CTAs/SM, fused bias + row L2-normalize.
// ---------------------------------------------------------------------------

#define NNODES   100000
#define INF      128
#define TWOK     256
#define OUTF     128

__device__ __half g_nh[(size_t)NNODES * INF];
__device__ int    g_rowstart[NNODES + 1];
__device__ __align__(128) unsigned char g_Wh_img[65536];

// ---------------------------------------------------------------------------
// helpers
// ---------------------------------------------------------------------------
__device__ __forceinline__ uint32_t smem_u32(const void* p) {
    uint32_t a;
    asm("{ .reg .u64 t; cvta.to.shared.u64 t, %1; cvt.u32.u64 %0, t; }"
        : "=r"(a) : "l"(p));
    return a;
}
__device__ __forceinline__ uint32_t sw128(uint32_t off) {
    return off ^ ((off >> 3) & 0x70);
}
__device__ __forceinline__ void ldsm_x4(uint32_t& r0, uint32_t& r1,
                                        uint32_t& r2, uint32_t& r3, uint32_t a) {
    asm volatile("ldmatrix.sync.aligned.m8n8.x4.shared.b16 {%0,%1,%2,%3}, [%4];"
                 : "=r"(r0), "=r"(r1), "=r"(r2), "=r"(r3) : "r"(a));
}
__device__ __forceinline__ void mma_f16(float* c, const uint32_t* a,
                                        const uint32_t* b) {
    asm volatile(
        "mma.sync.aligned.m16n8k16.row.col.f32.f16.f16.f32 "
        "{%0,%1,%2,%3}, {%4,%5,%6,%7}, {%8,%9}, {%0,%1,%2,%3};"
        : "+f"(c[0]), "+f"(c[1]), "+f"(c[2]), "+f"(c[3])
        : "r"(a[0]), "r"(a[1]), "r"(a[2]), "r"(a[3]), "r"(b[0]), "r"(b[1]));
}
#define CP_ASYNC16(dst, src) \
    asm volatile("cp.async.cg.shared.global [%0], [%1], 16;" :: "r"(dst), "l"(src))
#define CP_ASYNC16Z(dst, src, sz) \
    asm volatile("cp.async.cg.shared.global [%0], [%1], 16, %2;" \
                 :: "r"(dst), "l"(src), "r"(sz))
#define CP_COMMIT() asm volatile("cp.async.commit_group;" ::: "memory")
#define CP_WAIT1()  asm volatile("cp.async.wait_group 1;" ::: "memory")
#define CP_WAIT0()  asm volatile("cp.async.wait_group 0;" ::: "memory")

// ---------------------------------------------------------------------------
// K1: W fp16 image (tiny).
// ---------------------------------------------------------------------------
__global__ void prep_kernel(const float* __restrict__ W) {
    int i = blockIdx.x * blockDim.x + threadIdx.x;   // 0..8191 float4s
    int row   = i >> 6;
    int kf    = i & 63;
    int chunk = kf >> 4;
    int k4    = kf & 15;
    float4 wv = *reinterpret_cast<const float4*>(W + row * TWOK + chunk * 64 + k4 * 4);
    __half2 h0 = __floats2half2_rn(wv.x, wv.y);
    __half2 h1 = __floats2half2_rn(wv.z, wv.w);
    uint32_t off = chunk * 16384 + sw128((uint32_t)(row * 128 + k4 * 8));
    *reinterpret_cast<uint2*>(g_Wh_img + off) =
        make_uint2(*reinterpret_cast<uint32_t*>(&h0),
                   *reinterpret_cast<uint32_t*>(&h1));
}

// ---------------------------------------------------------------------------
// K1b: CSR gap-fill from sorted rows; last thread also fills tail rows.
// ---------------------------------------------------------------------------
__global__ void rowidx_kernel(const int* __restrict__ rows, int E, int N) {
    int e = blockIdx.x * blockDim.x + threadIdx.x;
    if (e >= E) return;
    int r = __ldg(rows + e);
    int prev = (e == 0) ? -1 : __ldg(rows + e - 1);
    if (r != prev) {
        for (int q = prev + 1; q <= r; q++) g_rowstart[q] = e;
    }
    if (e == E - 1) {
        for (int q = r + 1; q <= N; q++) g_rowstart[q] = E;
    }
}

// ---------------------------------------------------------------------------
// K2: SpMM, warp per row (round-9 proven body). Lane owns dims [4l,4l+4).
// Coalesced 32-edge metadata loads, 2-way shfl broadcast, dual accumulators.
// ---------------------------------------------------------------------------
__global__ void spmm_kernel(const float* __restrict__ x,
                            const int*   __restrict__ cols,
                            const float* __restrict__ vals,
                            int N) {
    int warp = (blockIdx.x * blockDim.x + threadIdx.x) >> 5;
    int lane = threadIdx.x & 31;
    if (warp >= N) return;
    int row = warp;

    int s  = __ldg(g_rowstart + row);
    int en = __ldg(g_rowstart + row + 1);

    const float4* x4 = reinterpret_cast<const float4*>(x);
    float4 acc0 = make_float4(0.f, 0.f, 0.f, 0.f);
    float4 acc1 = make_float4(0.f, 0.f, 0.f, 0.f);

    for (int e0 = s; e0 < en; e0 += 32) {
        int   idx = e0 + lane;
        bool  vd  = idx < en;
        int   c0  = vd ? __ldg(cols + idx) : 0;
        float v0  = vd ? __ldg(vals + idx) : 0.f;
        int n = min(32, en - e0);
        int j = 0;
        for (; j + 1 < n; j += 2) {
            int   cja = __shfl_sync(0xffffffffu, c0, j);
            float vja = __shfl_sync(0xffffffffu, v0, j);
            int   cjb = __shfl_sync(0xffffffffu, c0, j + 1);
            float vjb = __shfl_sync(0xffffffffu, v0, j + 1);
            float4 xa = x4[(size_t)cja * 32 + lane];
            float4 xb = x4[(size_t)cjb * 32 + lane];
            acc0.x = fmaf(vja, xa.x, acc0.x);
            acc0.y = fmaf(vja, xa.y, acc0.y);
            acc0.z = fmaf(vja, xa.z, acc0.z);
            acc0.w = fmaf(vja, xa.w, acc0.w);
            acc1.x = fmaf(vjb, xb.x, acc1.x);
            acc1.y = fmaf(vjb, xb.y, acc1.y);
            acc1.z = fmaf(vjb, xb.z, acc1.z);
            acc1.w = fmaf(vjb, xb.w, acc1.w);
        }
        if (j < n) {
            int   cja = __shfl_sync(0xffffffffu, c0, j);
            float vja = __shfl_sync(0xffffffffu, v0, j);
            float4 xa = x4[(size_t)cja * 32 + lane];
            acc0.x = fmaf(vja, xa.x, acc0.x);
            acc0.y = fmaf(vja, xa.y, acc0.y);
            acc0.z = fmaf(vja, xa.z, acc0.z);
            acc0.w = fmaf(vja, xa.w, acc0.w);
        }
    }

    acc0.x += acc1.x; acc0.y += acc1.y; acc0.z += acc1.z; acc0.w += acc1.w;

    __half2 h0 = __floats2half2_rn(acc0.x, acc0.y);
    __half2 h1 = __floats2half2_rn(acc0.z, acc0.w);
    reinterpret_cast<uint2*>(g_nh)[(size_t)row * 32 + lane] =
        make_uint2(*reinterpret_cast<uint32_t*>(&h0),
                   *reinterpret_cast<uint32_t*>(&h1));
}

// ---------------------------------------------------------------------------
// K3: fp16 HMMA GEMM + bias + L2 normalize.
//   Chunks 0-1: inline fp32 x load + cvt + swizzled STS (staging regs retire
//   before accumulators go live). Chunks 2-3: cp.async from g_nh.
// ---------------------------------------------------------------------------
#define SM_W    0
#define SM_A    65536                 // 2 stages x 16384
#define SM_BIAS (SM_A + 32768)
#define SM_RSS  (SM_BIAS + 512)
#define SM_TOTAL (SM_RSS + 2048)

__global__ void __launch_bounds__(256, 2)
gemm_norm_kernel(const float* __restrict__ x,
                 const float* __restrict__ b,
                 float* __restrict__ out,
                 int N) {
    extern __shared__ char smem[];
    uint32_t sb = smem_u32(smem);
    float* bias = reinterpret_cast<float*>(smem + SM_BIAS);
    float (*rss)[128] = reinterpret_cast<float (*)[128]>(smem + SM_RSS);

    int t    = threadIdx.x;
    int wid  = t >> 5;
    int lane = t & 31;
    int warp_m = wid & 1;
    int warp_n = wid >> 1;
    int rowBase = blockIdx.x * 128;

    // W image -> smem (async, group0)
    #pragma unroll
    for (int j = 0; j < 16; j++)
        CP_ASYNC16(sb + SM_W + t * 16 + j * 4096, g_Wh_img + t * 16 + j * 4096);
    CP_COMMIT();

    // stage chunks 0,1 from fp32 x: thread covers units i = t+256j (j<4),
    // r = i>>3 (row 0..127), u8 = i&7 (16B fp16 unit = 8 k-dims)
    #pragma unroll
    for (int c = 0; c < 2; c++) {
        char* dstb = smem + SM_A + c * 16384;
        #pragma unroll
        for (int j = 0; j < 4; j++) {
            int i  = t + 256 * j;
            int r  = i >> 3;
            int u8 = i & 7;
            int gr = rowBase + r;
            float4 f0, f1;
            if (gr < N) {
                const float* src = x + (size_t)gr * INF + c * 64 + u8 * 8;
                f0 = *reinterpret_cast<const float4*>(src);
                f1 = *reinterpret_cast<const float4*>(src + 4);
            } else {
                f0 = make_float4(0.f, 0.f, 0.f, 0.f);
                f1 = f0;
            }
            __half2 h0 = __floats2half2_rn(f0.x, f0.y);
            __half2 h1 = __floats2half2_rn(f0.z, f0.w);
            __half2 h2 = __floats2half2_rn(f1.x, f1.y);
            __half2 h3 = __floats2half2_rn(f1.z, f1.w);
            uint4 o;
            o.x = *reinterpret_cast<uint32_t*>(&h0);
            o.y = *reinterpret_cast<uint32_t*>(&h1);
            o.z = *reinterpret_cast<uint32_t*>(&h2);
            o.w = *reinterpret_cast<uint32_t*>(&h3);
            *reinterpret_cast<uint4*>(dstb + sw128((uint32_t)(r * 128 + u8 * 16))) = o;
        }
    }

    if (t < OUTF) bias[t] = __ldg(b + t);

    const char* nb = reinterpret_cast<const char*>(g_nh);
    auto stageNH = [&](int c) {       // c = 2 or 3, dest buf = c&1
        const char* srcb = nb + (c - 2) * 128;
        uint32_t dstb = sb + SM_A + (c & 1) * 16384;
        #pragma unroll
        for (int j = 0; j < 4; j++) {
            int i  = t + 256 * j;
            int r  = i >> 3;
            int u8 = i & 7;
            int gr = rowBase + r;
            uint32_t sz = (gr < N) ? 16u : 0u;
            CP_ASYNC16Z(dstb + sw128((uint32_t)(r * 128 + u8 * 16)),
                        srcb + (size_t)gr * 256 + u8 * 16, sz);
        }
    };

    float acc[4][4][4];
    #pragma unroll
    for (int mi = 0; mi < 4; mi++)
        #pragma unroll
        for (int ni = 0; ni < 4; ni++)
            #pragma unroll
            for (int r = 0; r < 4; r++) acc[mi][ni][r] = 0.f;

    int aRow  = warp_m * 64 + (lane & 15);
    int aK8   = (lane >> 4) * 8;
    int bRowX = warp_n * 32 + (lane & 7) + ((lane >> 4) & 1) * 8;
    int bK8   = ((lane >> 3) & 1) * 8;

    auto compute = [&](int c) {
        uint32_t aBuf  = sb + SM_A + (c & 1) * 16384;
        uint32_t wBase = sb + SM_W + c * 16384;
        #pragma unroll
        for (int kk = 0; kk < 64; kk += 16) {
            uint32_t a[4][4], bb[4][2];
            #pragma unroll
            for (int mi = 0; mi < 4; mi++) {
                uint32_t off = sw128((uint32_t)((aRow + mi * 16) * 128
                                                + (kk + aK8) * 2));
                ldsm_x4(a[mi][0], a[mi][1], a[mi][2], a[mi][3], aBuf + off);
            }
            #pragma unroll
            for (int p = 0; p < 2; p++) {
                uint32_t off = sw128((uint32_t)((bRowX + p * 16) * 128
                                                + (kk + bK8) * 2));
                ldsm_x4(bb[2*p][0], bb[2*p][1], bb[2*p+1][0], bb[2*p+1][1],
                        wBase + off);
            }
            #pragma unroll
            for (int mi = 0; mi < 4; mi++)
                #pragma unroll
                for (int ni = 0; ni < 4; ni++)
                    mma_f16(acc[mi][ni], a[mi], bb[ni]);
        }
    };

    CP_WAIT0();            // W resident
    __syncthreads();       // c0/c1 STS visible
    compute(0);
    __syncthreads();       // buf0 free
    stageNH(2); CP_COMMIT();       // group: c2
    compute(1);
    __syncthreads();       // buf1 free
    stageNH(3); CP_COMMIT();       // group: c3
    CP_WAIT1();            // c2 arrived
    __syncthreads();
    compute(2);
    CP_WAIT0();            // c3 arrived
    __syncthreads();
    compute(3);

    // ---- epilogue ----
    int colBase = warp_n * 32 + 2 * (lane & 3);
    #pragma unroll
    for (int mi = 0; mi < 4; mi++)
        #pragma unroll
        for (int ni = 0; ni < 4; ni++) {
            float b0 = bias[colBase + ni * 8];
            float b1 = bias[colBase + ni * 8 + 1];
            acc[mi][ni][0] += b0;  acc[mi][ni][1] += b1;
            acc[mi][ni][2] += b0;  acc[mi][ni][3] += b1;
        }

    #pragma unroll
    for (int mi = 0; mi < 4; mi++) {
        #pragma unroll
        for (int half = 0; half < 2; half++) {
            float s = 0.f;
            #pragma unroll
            for (int ni = 0; ni < 4; ni++) {
                float c0 = acc[mi][ni][half * 2 + 0];
                float c1 = acc[mi][ni][half * 2 + 1];
                s = fmaf(c0, c0, s);
                s = fmaf(c1, c1, s);
            }
            s += __shfl_xor_sync(0xffffffffu, s, 1);
            s += __shfl_xor_sync(0xffffffffu, s, 2);
            if ((lane & 3) == 0)
                rss[warp_n][warp_m * 64 + mi * 16 + half * 8 + (lane >> 2)] = s;
        }
    }
    __syncthreads();

    float2* out2 = reinterpret_cast<float2*>(out);
    #pragma unroll
    for (int mi = 0; mi < 4; mi++) {
        #pragma unroll
        for (int half = 0; half < 2; half++) {
            int rl  = warp_m * 64 + mi * 16 + half * 8 + (lane >> 2);
            int row = rowBase + rl;
            if (row < N) {
                float ss = rss[0][rl] + rss[1][rl] + rss[2][rl] + rss[3][rl];
                float scale = 1.f / fmaxf(sqrtf(ss), 1e-12f);
                #pragma unroll
                for (int ni = 0; ni < 4; ni++) {
                    float2 o;
                    o.x = acc[mi][ni][half * 2 + 0] * scale;
                    o.y = acc[mi][ni][half * 2 + 1] * scale;
                    out2[(size_t)row * 64 + (colBase + ni * 8) / 2] = o;
                }
            }
        }
    }
}

// ---------------------------------------------------------------------------
// Launch
// ---------------------------------------------------------------------------
extern "C" void kernel_launch(void* const* d_in, const int* in_sizes, int n_in,
                              void* d_out, int out_size) {
    const float* x    = (const float*)d_in[0];
    const int*   rows = (const int*)  d_in[1];
    const int*   cols = (const int*)  d_in[2];
    const float* vals = (const float*)d_in[3];
    const float* W    = (const float*)d_in[4];
    const float* b    = (const float*)d_in[5];
    float*       out  = (float*)d_out;

    int N = in_sizes[0] / INF;
    int E = in_sizes[1];

    cudaFuncSetAttribute(gemm_norm_kernel,
                         cudaFuncAttributeMaxDynamicSharedMemorySize, SM_TOTAL);

    // K1: W image (tiny)
    prep_kernel<<<32, 256>>>(W);

    // K1b: CSR row_start gap-fill (incl. tail + [N])
    rowidx_kernel<<<(E + 255) / 256, 256>>>(rows, E, N);

    // K2: SpMM (round-9 proven body)
    int blocks = (N * 32 + 255) / 256;
    spmm_kernel<<<blocks, 256>>>(x, cols, vals, N);

    // K3: fp16 HMMA GEMM + bias + normalize (inline x cvt for chunks 0-1)
    gemm_norm_kernel<<<(N + 127) / 128, 256, SM_TOTAL>>>(x, b, out, N);
}